// round 12
// baseline (speedup 1.0000x reference)
#include <cuda_runtime.h>
#include <mma.h>
#include <cstdint>

using namespace nvcuda;

#define BB    4
#define CCH   256
#define HH    128
#define WWI   416
#define DDI   81
#define PLANE (HH*WWI)
#define MAXD  40

#define MT    64             // M tile
#define KC    16             // channels per chunk (double-buffered)
#define NCH   16             // 256/16
#define NTH   256

#define A_LD  24             // fp32 [m][k] lead dim (mult of 4; rows 0-3 tile all 32 banks)
#define B_LD  156            // fp32 [k][n] lead dim (mult of 4)
#define A_BYTES (MT * A_LD * 4)            // 6144
#define B_BYTES (KC * B_LD * 4)            // 9984
#define BUF_BYTES (A_BYTES + B_BYTES)      // 16128
#define SMEM_BYTES (2 * BUF_BYTES)         // 32256

#define D_LD  148            // D staging stride (149-word row step, odd -> conflict-free)

__device__ __forceinline__ void cpa16(uint32_t saddr, const void* gaddr, uint32_t srcsz) {
    asm volatile("cp.async.cg.shared.global [%0], [%1], 16, %2;\n"
                 :: "r"(saddr), "l"(gaddr), "r"(srcsz));
}
__device__ __forceinline__ void cpa4(uint32_t saddr, const void* gaddr) {
    asm volatile("cp.async.ca.shared.global [%0], [%1], 4;\n"
                 :: "r"(saddr), "l"(gaddr));
}

__global__ __launch_bounds__(NTH, 4)
void corr_tf32(const float* __restrict__ left,
               const float* __restrict__ right,
               float* __restrict__ out) {
    extern __shared__ __align__(16) char smem[];
    uint32_t sbase;
    asm("{ .reg .u64 t; cvta.to.shared.u64 t, %1; cvt.u32.u64 %0, t; }" : "=r"(sbase) : "l"(smem));

    const int tid  = threadIdx.x;
    const int wid  = tid >> 5;
    const int tile = blockIdx.x;                  // 0..6
    const int m0   = (tile == 6) ? 352 : tile * MT;
    const int h    = blockIdx.y, b = blockIdx.z;
    const float* lbase = left  + ((size_t)b * CCH * HH + h) * WWI;
    const float* rbase = right + ((size_t)b * CCH * HH + h) * WWI;

    // warp mapping: wmid = 16-row m stripe; wnid picks 3 of its 6 band n-tiles
    const int wmid  = wid & 3;
    const int wnid  = wid >> 2;
    const int nbase = wmid * 16 + wnid * 48;

    // ---- chunk fill via cp.async (raw fp32 into smem) ----
    auto fill = [&](int c, int buf) {
        const int c0 = c * KC;
        const uint32_t sb = sbase + buf * BUF_BYTES;
        // A transposed copies: As[m][k] = L[c0+k, m0+m]; gmem coalesced in m
        #pragma unroll
        for (int i = 0; i < 4; i++) {
            const int idx = tid + i * NTH;        // 0..1023
            const int k   = idx >> 6;             // 0..15
            const int m   = idx & 63;
            cpa4(sb + (uint32_t)(m * A_LD + k) * 4,
                 lbase + (size_t)(c0 + k) * PLANE + m0 + m);
        }
        // B: Bs[k][n] = R[c0+k, m0-40+n], zero-fill OOB (16k x 36 float4)
        #pragma unroll
        for (int i = 0; i < 3; i++) {
            const int idx = tid + i * NTH;
            if (idx < 576) {
                const int k  = idx / 36;
                const int n4 = (idx - k * 36) * 4;
                const int wb = m0 - MAXD + n4;
                const bool inb = (wb >= 0) && (wb + 3 < WWI);
                const float* src = rbase + (size_t)(c0 + k) * PLANE + (inb ? wb : 0);
                cpa16(sb + A_BYTES + (uint32_t)(k * B_LD + n4) * 4, src, inb ? 16u : 0u);
            }
        }
        asm volatile("cp.async.commit_group;\n" ::: "memory");
    };

    wmma::fragment<wmma::accumulator, 16, 16, 8, float> acc[3];
    #pragma unroll
    for (int j = 0; j < 3; j++) wmma::fill_fragment(acc[j], 0.0f);

    fill(0, 0);

    for (int c = 0; c < NCH; c++) {
        const int buf = c & 1;
        if (c + 1 < NCH) {
            fill(c + 1, buf ^ 1);
            asm volatile("cp.async.wait_group 1;\n" ::: "memory");
        } else {
            asm volatile("cp.async.wait_group 0;\n" ::: "memory");
        }
        __syncthreads();

        const float* As = (const float*)(smem + buf * BUF_BYTES);
        const float* Bs = (const float*)(smem + buf * BUF_BYTES + A_BYTES);

        #pragma unroll
        for (int kt = 0; kt < 2; kt++) {          // two k=8 steps per 16-chunk
            wmma::fragment<wmma::matrix_a, 16, 16, 8, wmma::precision::tf32, wmma::row_major> af;
            wmma::load_matrix_sync(af, As + (wmid * 16) * A_LD + kt * 8, A_LD);
            #pragma unroll
            for (int e = 0; e < af.num_elements; e++) af.x[e] = wmma::__float_to_tf32(af.x[e]);
            #pragma unroll
            for (int j = 0; j < 3; j++) {
                wmma::fragment<wmma::matrix_b, 16, 16, 8, wmma::precision::tf32, wmma::row_major> bf;
                wmma::load_matrix_sync(bf, Bs + kt * 8 * B_LD + nbase + j * 16, B_LD);
                #pragma unroll
                for (int e = 0; e < bf.num_elements; e++) bf.x[e] = wmma::__float_to_tf32(bf.x[e]);
                wmma::mma_sync(acc[j], af, bf, acc[j]);
            }
        }
        __syncthreads();   // fragment reads done before this buffer is refilled
    }

    // ---- scale by 1/256 (exact power of two) ----
    #pragma unroll
    for (int j = 0; j < 3; j++)
        #pragma unroll
        for (int e = 0; e < acc[j].num_elements; e++) acc[j].x[e] *= (1.0f / 256.0f);

    // ---- epilogue in two m-half passes; Ds = [32][148] f32 fits smem ----
    float* Ds = (float*)smem;
    const int ms = (tile == 6) ? 32 : 0;          // mask overlap with tile 5
    #pragma unroll
    for (int half = 0; half < 2; half++) {
        if ((wmid >> 1) == half) {
            const int rrow = (wmid & 1) * 16;
            #pragma unroll
            for (int j = 0; j < 3; j++)
                wmma::store_matrix_sync(Ds + rrow * D_LD + nbase + j * 16,
                                        acc[j], D_LD, wmma::mem_row_major);
        }
        __syncthreads();

        const int ml = tid & 31;
        const int m  = half * 32 + ml;
        if (m >= ms) {
            for (int d = tid >> 5; d < DDI; d += 8) {
                out[(((size_t)b * DDI + d) * HH + h) * WWI + m0 + m] = Ds[ml * D_LD + m + d];
            }
        }
        __syncthreads();
    }
}

extern "C" void kernel_launch(void* const* d_in, const int* in_sizes, int n_in,
                              void* d_out, int out_size) {
    const float* left  = (const float*)d_in[0];
    const float* right = (const float*)d_in[1];
    float* out = (float*)d_out;
    (void)in_sizes; (void)n_in; (void)out_size;

    cudaFuncSetAttribute(corr_tf32, cudaFuncAttributeMaxDynamicSharedMemorySize, SMEM_BYTES);
    dim3 grid(7, HH, BB);    // (m-tiles, h, b) = 3584 CTAs
    corr_tf32<<<grid, NTH, SMEM_BYTES>>>(left, right, out);
}

// round 13
// speedup vs baseline: 2.4068x; 2.4068x over previous
#include <cuda_runtime.h>
#include <cuda_fp16.h>
#include <mma.h>
#include <cstdint>

using namespace nvcuda;

#define BB    4
#define CCH   256
#define HH    128
#define WWI   416
#define DDI   81
#define PLANE (HH*WWI)
#define MAXD  40

#define MT    64             // M tile
#define KC    32             // channels per chunk (double-buffered)
#define NCH   8              // 256/32
#define NTH   256

#define A_LD  72             // [k][m] halves
#define B_LD  152            // [k][n] halves
#define A_BYTES (KC * A_LD * 2)          // 4608
#define B_BYTES (KC * B_LD * 2)          // 9728
#define BUF_BYTES (A_BYTES + B_BYTES)    // 14336
#define SMEM_BYTES (2 * BUF_BYTES)       // 28672

#define D_LD  148            // D staging stride (149-word row step, odd -> conflict-free)

__global__ __launch_bounds__(NTH, 3)
void corr_pipe(const float* __restrict__ left,
               const float* __restrict__ right,
               float* __restrict__ out) {
    extern __shared__ __align__(16) char smem[];

    const int tid  = threadIdx.x;
    const int wid  = tid >> 5;
    const int tile = blockIdx.x;                  // 0..6
    const int m0   = (tile == 6) ? 352 : tile * MT;
    const int h    = blockIdx.y, b = blockIdx.z;
    const float* lbase = left  + ((size_t)b * CCH * HH + h) * WWI;
    const float* rbase = right + ((size_t)b * CCH * HH + h) * WWI;

    // warp mapping: wmid = 16-row m stripe; wnid picks 3 of its 6 band n-tiles
    const int wmid  = wid & 3;
    const int wnid  = wid >> 2;
    const int nbase = wmid * 16 + wnid * 48;

    // ---- register staging for one chunk ----
    float4 rA[2];
    float4 rB[5];

    auto load_chunk = [&](int c) {
        const int c0 = c * KC;
        #pragma unroll
        for (int i = 0; i < 2; i++) {             // A: 512 float4 (32k x 16)
            const int idx = tid + i * NTH;
            const int k   = idx >> 4;             // 0..31
            const int mi  = (idx & 15) * 4;       // 0..60
            rA[i] = *(const float4*)(lbase + (size_t)(c0 + k) * PLANE + m0 + mi);
        }
        #pragma unroll
        for (int i = 0; i < 5; i++) {             // B: 1152 float4 (32k x 36)
            const int idx = tid + i * NTH;
            if (idx < 1152) {
                const int k  = idx / 36;
                const int n4 = (idx - k * 36) * 4;
                const int wb = m0 - MAXD + n4;
                rB[i] = (wb >= 0 && wb + 3 < WWI)
                      ? *(const float4*)(rbase + (size_t)(c0 + k) * PLANE + wb)
                      : make_float4(0.f, 0.f, 0.f, 0.f);
            }
        }
    };

    auto store_chunk = [&](int buf) {
        __half* As = (__half*)(smem + buf * BUF_BYTES);
        __half* Bs = (__half*)(smem + buf * BUF_BYTES + A_BYTES);
        #pragma unroll
        for (int i = 0; i < 2; i++) {
            const int idx = tid + i * NTH;
            const int k   = idx >> 4;
            const int mi  = (idx & 15) * 4;
            __half2 h0 = __floats2half2_rn(rA[i].x, rA[i].y);
            __half2 h1 = __floats2half2_rn(rA[i].z, rA[i].w);
            *(uint2*)(As + k * A_LD + mi) = make_uint2(*(uint32_t*)&h0, *(uint32_t*)&h1);
        }
        #pragma unroll
        for (int i = 0; i < 5; i++) {
            const int idx = tid + i * NTH;
            if (idx < 1152) {
                const int k  = idx / 36;
                const int n4 = (idx - k * 36) * 4;
                __half2 h0 = __floats2half2_rn(rB[i].x, rB[i].y);
                __half2 h1 = __floats2half2_rn(rB[i].z, rB[i].w);
                *(uint2*)(Bs + k * B_LD + n4) = make_uint2(*(uint32_t*)&h0, *(uint32_t*)&h1);
            }
        }
    };

    wmma::fragment<wmma::accumulator, 16, 16, 16, float> acc[3];
    #pragma unroll
    for (int j = 0; j < 3; j++) wmma::fill_fragment(acc[j], 0.0f);

    // prologue: chunk 0 into buffer 0
    load_chunk(0);
    store_chunk(0);
    __syncthreads();

    for (int c = 0; c < NCH; c++) {
        const int buf = c & 1;

        // issue next chunk's global loads BEFORE the MMA work (latency overlap)
        if (c + 1 < NCH) load_chunk(c + 1);

        const __half* As = (const __half*)(smem + buf * BUF_BYTES);
        const __half* Bs = (const __half*)(smem + buf * BUF_BYTES + A_BYTES);
        #pragma unroll
        for (int kt = 0; kt < KC / 16; kt++) {
            wmma::fragment<wmma::matrix_a, 16, 16, 16, __half, wmma::col_major> af;
            wmma::load_matrix_sync(af, As + kt * 16 * A_LD + wmid * 16, A_LD);
            #pragma unroll
            for (int j = 0; j < 3; j++) {
                wmma::fragment<wmma::matrix_b, 16, 16, 16, __half, wmma::row_major> bf;
                wmma::load_matrix_sync(bf, Bs + kt * 16 * B_LD + nbase + j * 16, B_LD);
                wmma::mma_sync(acc[j], af, bf, acc[j]);
            }
        }

        // convert + store next chunk into the other buffer (LDGs have landed by now)
        if (c + 1 < NCH) store_chunk(buf ^ 1);
        __syncthreads();
    }

    // ---- scale by 1/256 (exact power of two) ----
    #pragma unroll
    for (int j = 0; j < 3; j++)
        #pragma unroll
        for (int e = 0; e < acc[j].num_elements; e++) acc[j].x[e] *= (1.0f / 256.0f);

    // ---- epilogue in two m-half passes; Ds = [32][148] f32 = 18944 B fits ----
    float* Ds = (float*)smem;
    const int ms = (tile == 6) ? 32 : 0;          // mask overlap with tile 5
    #pragma unroll
    for (int half = 0; half < 2; half++) {
        if ((wmid >> 1) == half) {
            const int rrow = (wmid & 1) * 16;
            #pragma unroll
            for (int j = 0; j < 3; j++)
                wmma::store_matrix_sync(Ds + rrow * D_LD + nbase + j * 16,
                                        acc[j], D_LD, wmma::mem_row_major);
        }
        __syncthreads();

        const int ml = tid & 31;
        const int m  = half * 32 + ml;
        if (m >= ms) {
            for (int d = tid >> 5; d < DDI; d += 8) {
                out[(((size_t)b * DDI + d) * HH + h) * WWI + m0 + m] = Ds[ml * D_LD + m + d];
            }
        }
        __syncthreads();
    }
}

extern "C" void kernel_launch(void* const* d_in, const int* in_sizes, int n_in,
                              void* d_out, int out_size) {
    const float* left  = (const float*)d_in[0];
    const float* right = (const float*)d_in[1];
    float* out = (float*)d_out;
    (void)in_sizes; (void)n_in; (void)out_size;

    cudaFuncSetAttribute(corr_pipe, cudaFuncAttributeMaxDynamicSharedMemorySize, SMEM_BYTES);
    dim3 grid(7, HH, BB);    // (m-tiles, h, b) = 3584 CTAs
    corr_pipe<<<grid, NTH, SMEM_BYTES>>>(left, right, out);
}